// round 4
// baseline (speedup 1.0000x reference)
#include <cuda_runtime.h>

#define D        64
#define HH       64
#define D_INPUT  2145
#define PATHS_PER_BLOCK 64    // 128 threads, 2 threads per path
#define TPB      128
#define OBS_PAD  68           // 16B-aligned rows

typedef unsigned long long ull;

__device__ float g_wt[HH][D * D];   // upper-triangular, ZERO below diagonal (load-bearing!)
__device__ float g_wl[HH][D];       // linear weights

// ---------------------------------------------------------------------------
// packed f32x2 helpers (sm_103a)
// ---------------------------------------------------------------------------
__device__ __forceinline__ ull f2fma(ull a, ull b, ull c) {
    ull d;
    asm("fma.rn.f32x2 %0, %1, %2, %3;" : "=l"(d) : "l"(a), "l"(b), "l"(c));
    return d;
}
__device__ __forceinline__ ull f2add(ull a, ull b) {
    ull d;
    asm("add.rn.f32x2 %0, %1, %2;" : "=l"(d) : "l"(a), "l"(b));
    return d;
}
__device__ __forceinline__ ull dup_lo(ull p) { return (p & 0xffffffffull) | (p << 32); }
__device__ __forceinline__ ull dup_hi(ull p) { return (p >> 32) | (p & 0xffffffff00000000ull); }
__device__ __forceinline__ float hsum(ull p) {
    float lo = __uint_as_float((unsigned)(p & 0xffffffffull));
    float hi = __uint_as_float((unsigned)(p >> 32));
    return lo + hi;
}

// ---------------------------------------------------------------------------
// Prep: unpack packed-triangular weights into regular [i][j] rows, zero below
// diagonal. weights[h][64 + base(i) + (j-i)], base(i) = i*64 - i*(i-1)/2.
// ---------------------------------------------------------------------------
__global__ void prep_kernel(const float* __restrict__ w) {
    const int h = blockIdx.x;
    const float* wh = w + (size_t)h * D_INPUT;
    for (int idx = threadIdx.x; idx < D * D; idx += blockDim.x) {
        const int i = idx >> 6;
        const int j = idx & 63;
        float v = 0.0f;
        if (j >= i) {
            const int base = i * D - (i * (i - 1)) / 2;
            v = wh[D + base + (j - i)];
        }
        g_wt[h][idx] = v;
    }
    if (threadIdx.x < D) g_wl[h][threadIdx.x] = wh[threadIdx.x];
}

// ---------------------------------------------------------------------------
// Main: block = (64-path tile, h), 128 threads. Thread pair (2k, 2k+1) shares
// path k: half s processes float4-chunks j4 with (j4 & 1) == s. Both halves
// start at hbase = (i>>3)*2 so trip counts are warp-uniform; any chunk fully
// below the diagonal is zero-filled and contributes nothing. Pair-reduce via
// shfl.bfly(1).
// ---------------------------------------------------------------------------
extern __shared__ float smem[];

__global__ __launch_bounds__(TPB, 4)
void vf_kernel(const float* __restrict__ obs,
               const float* __restrict__ biases,
               float* __restrict__ out) {
    const int h     = blockIdx.y;
    const int pbase = blockIdx.x * PATHS_PER_BLOCK;
    const int tid   = threadIdx.x;
    const int s     = tid & 1;        // which half of the path's work
    const int row   = tid >> 1;       // path within tile (0..63)

    float* s_w   = smem;              // 4096 floats (64 rows x 256B)
    float* s_wl  = smem + D * D;      // 64 floats
    float* s_obs = smem + D * D + D;  // 64 rows x OBS_PAD

    // --- Stage weights: 1024 float4, 8/thread
    {
        const float4* gw4 = reinterpret_cast<const float4*>(&g_wt[h][0]);
        float4*       sw4 = reinterpret_cast<float4*>(s_w);
        #pragma unroll
        for (int k = 0; k < 8; k++) sw4[tid + TPB * k] = gw4[tid + TPB * k];
        if (tid < D / 4)
            reinterpret_cast<float4*>(s_wl)[tid] =
                reinterpret_cast<const float4*>(&g_wl[h][0])[tid];
    }

    // --- Stage 64 obs rows: 1024 float4, 8/thread, coalesced 256B rows
    {
        #pragma unroll
        for (int k = 0; k < 8; k++) {
            const int f = tid + TPB * k;
            const int p = f >> 4;
            const int q = f & 15;
            const float4 v = reinterpret_cast<const float4*>(obs)
                [(size_t)(pbase + p) * (HH * D / 4) + (size_t)h * (D / 4) + q];
            *reinterpret_cast<float4*>(&s_obs[p * OBS_PAD + 4 * q]) = v;
        }
    }
    __syncthreads();

    // --- o-vector for this thread's path (both pair lanes read the same row)
    ull o[D / 2];
    {
        const ulonglong2* prow = reinterpret_cast<const ulonglong2*>(s_obs + row * OBS_PAD);
        #pragma unroll
        for (int m = 0; m < D / 4; m++) {
            const ulonglong2 a = prow[m];
            o[2 * m] = a.x; o[2 * m + 1] = a.y;
        }
    }

    // --- Linear term: half s takes ull entries m with (m & 1) == s
    ull acc = 0ull;
    {
        const ull* wl2 = reinterpret_cast<const ull*>(s_wl);
        #pragma unroll
        for (int m = 0; m < D / 2; m += 2)
            acc = f2fma(wl2[m + s], o[m + s], acc);
    }

    // --- Triangular quadratic term, split by chunk parity.
    // Row i: chunks j4 = hbase + s + 2c, c in [0, 8 - (i>>3)); hbase = (i>>3)*2.
    #pragma unroll
    for (int i = 0; i < D; i++) {
        const int hb    = (i >> 3) << 1;
        const int count = 8 - (i >> 3);
        const ulonglong2* wrow = reinterpret_cast<const ulonglong2*>(s_w + i * D);
        ull r0 = 0ull, r1 = 0ull;
        #pragma unroll
        for (int c = 0; c < count; c++) {
            const int j4 = hb + s + 2 * c;
            const ulonglong2 w = wrow[j4];
            r0 = f2fma(w.x, o[2 * j4],     r0);
            r1 = f2fma(w.y, o[2 * j4 + 1], r1);
        }
        const ull rt = f2add(r0, r1);
        const ull oi = (i & 1) ? dup_hi(o[i >> 1]) : dup_lo(o[i >> 1]);
        acc = f2fma(oi, rt, acc);
    }

    // --- Pair reduce + write (even lane of each pair)
    float a = hsum(acc);
    a += __shfl_xor_sync(0xffffffffu, a, 1);
    if (s == 0)
        out[(size_t)(pbase + row) * HH + h] = a + biases[h];
}

// ---------------------------------------------------------------------------
extern "C" void kernel_launch(void* const* d_in, const int* in_sizes, int n_in,
                              void* d_out, int out_size) {
    const float* obs = (const float*)d_in[0];
    const float* w   = (const float*)d_in[1];
    const float* b   = (const float*)d_in[2];
    float* out       = (float*)d_out;

    const int N = in_sizes[0] / (HH * D);   // 1024

    prep_kernel<<<HH, 512>>>(w);

    const int smem_bytes = (D * D + D + PATHS_PER_BLOCK * OBS_PAD) * (int)sizeof(float); // ~34 KB
    cudaFuncSetAttribute(vf_kernel, cudaFuncAttributeMaxDynamicSharedMemorySize, smem_bytes);

    dim3 grid(N / PATHS_PER_BLOCK, HH);     // (16, 64) = 1024 blocks x 4 warps
    vf_kernel<<<grid, TPB, smem_bytes>>>(obs, b, out);
}

// round 6
// speedup vs baseline: 1.3582x; 1.3582x over previous
#include <cuda_runtime.h>
#include <cuda_bf16.h>
#include <cstdint>

#define D        64
#define HH       64
#define D_INPUT  2145
#define TPB      128

typedef unsigned long long ull;

// Pre-swizzled (SW128) bf16 images of M = 1/2(Wu+Wu^T) (diag unhalved),
// split hi/lo. Row = n (output dim), col = k (reduction dim). 64 x 128B per h.
__device__ __align__(16) uint8_t g_Bh[HH][D * 128];
__device__ __align__(16) uint8_t g_Bl[HH][D * 128];
__device__ float g_wl[HH][D];

#define SWZ(off) ((off) ^ (((off) >> 3) & 0x70))

__device__ __forceinline__ uint32_t smem_u32(const void* p) {
    uint32_t a;
    asm("{ .reg .u64 t; cvta.to.shared.u64 t, %1; cvt.u32.u64 %0, t; }" : "=r"(a) : "l"(p));
    return a;
}
__device__ __forceinline__ void ldm_x4(uint32_t* r, uint32_t addr) {
    asm volatile("ldmatrix.sync.aligned.m8n8.x4.shared.b16 {%0,%1,%2,%3}, [%4];"
        : "=r"(r[0]), "=r"(r[1]), "=r"(r[2]), "=r"(r[3]) : "r"(addr));
}
__device__ __forceinline__ void mma_bf16(float* c, const uint32_t* a, const uint32_t* b) {
    asm volatile("mma.sync.aligned.m16n8k16.row.col.f32.bf16.bf16.f32 "
        "{%0,%1,%2,%3}, {%4,%5,%6,%7}, {%8,%9}, {%0,%1,%2,%3};"
        : "+f"(c[0]), "+f"(c[1]), "+f"(c[2]), "+f"(c[3])
        : "r"(a[0]), "r"(a[1]), "r"(a[2]), "r"(a[3]), "r"(b[0]), "r"(b[1]));
}

// ---------------------------------------------------------------------------
// Prep: build symmetric M, split to bf16 hi/lo, write SW128-swizzled images.
// Packed-triangular source: w[h][64 + base(i) + (j-i)], i<=j, base(i)=i*64-i(i-1)/2.
// ---------------------------------------------------------------------------
__global__ void prep_kernel(const float* __restrict__ w) {
    const int h = blockIdx.x;
    const float* wh = w + (size_t)h * D_INPUT;
    for (int idx = threadIdx.x; idx < D * D; idx += blockDim.x) {
        const int n = idx >> 6;      // image row (output dim)
        const int k = idx & 63;      // image col (reduction dim)
        const int i = k < n ? k : n;
        const int j = k < n ? n : k;
        const float v = wh[D + i * D - (i * (i - 1)) / 2 + (j - i)];
        const float m = (k == n) ? v : 0.5f * v;
        const __nv_bfloat16 hi = __float2bfloat16_rn(m);
        const __nv_bfloat16 lo = __float2bfloat16_rn(m - __bfloat162float(hi));
        const uint32_t sw = SWZ((uint32_t)(n * 128 + k * 2));
        *(__nv_bfloat16*)(&g_Bh[h][sw]) = hi;
        *(__nv_bfloat16*)(&g_Bl[h][sw]) = lo;
    }
    if (threadIdx.x < D) g_wl[h][threadIdx.x] = wh[threadIdx.x];
}

// ---------------------------------------------------------------------------
// Main: block = (128-path tile, h), 128 threads / 4 warps. Warp computes a
// 32-row strip of T = O*M via mma.sync (3 split-bf16 passes), epilogue folds
// val = b + sum_d o_d*(wl_d + T_d) with a 4-lane shfl reduce.
// ---------------------------------------------------------------------------
#define SM_AOH  0                       // 128 x 128B bf16 hi (SW128)
#define SM_AOL  16384                   // 128 x 128B bf16 lo
#define SM_BSH  32768                   // 64 x 128B M hi
#define SM_BSL  40960                   // 64 x 128B M lo
#define SM_WL   49152                   // 64 fp32
#define SM_TOT  (SM_WL + 256)

extern __shared__ char smem[];

__global__ __launch_bounds__(TPB)
void vf_kernel(const float* __restrict__ obs,
               const float* __restrict__ biases,
               float* __restrict__ out) {
    const int h     = blockIdx.y;
    const int pbase = blockIdx.x * 128;
    const int tid   = threadIdx.x;
    const int wid   = tid >> 5;
    const int lid   = tid & 31;
    const uint32_t sbase = smem_u32(smem);

    // --- Stage M images (pre-swizzled in gmem) + linear weights
    {
        const float4* bh4 = reinterpret_cast<const float4*>(&g_Bh[h][0]);
        const float4* bl4 = reinterpret_cast<const float4*>(&g_Bl[h][0]);
        float4* sh4 = reinterpret_cast<float4*>(smem + SM_BSH);
        float4* sl4 = reinterpret_cast<float4*>(smem + SM_BSL);
        #pragma unroll
        for (int k = 0; k < 4; k++) {
            sh4[tid + TPB * k] = bh4[tid + TPB * k];
            sl4[tid + TPB * k] = bl4[tid + TPB * k];
        }
        if (tid < D / 4)
            reinterpret_cast<float4*>(smem + SM_WL)[tid] =
                reinterpret_cast<const float4*>(&g_wl[h][0])[tid];
    }

    // --- Stage obs tile: fp32 coalesced loads -> bf16 hi/lo, swizzled stores
    {
        #pragma unroll
        for (int k = 0; k < 16; k++) {
            const int f = tid + TPB * k;
            const int p = f >> 4;
            const int q = f & 15;
            const float4 v = reinterpret_cast<const float4*>(obs)
                [(size_t)(pbase + p) * (HH * D / 4) + (size_t)h * (D / 4) + q];
            __nv_bfloat16 hb[4], lb[4];
            const float vf[4] = {v.x, v.y, v.z, v.w};
            #pragma unroll
            for (int e = 0; e < 4; e++) {
                hb[e] = __float2bfloat16_rn(vf[e]);
                lb[e] = __float2bfloat16_rn(vf[e] - __bfloat162float(hb[e]));
            }
            const uint32_t sw = SWZ((uint32_t)(p * 128 + q * 8));
            *reinterpret_cast<ull*>(smem + SM_AOH + sw) = *reinterpret_cast<ull*>(hb);
            *reinterpret_cast<ull*>(smem + SM_AOL + sw) = *reinterpret_cast<ull*>(lb);
        }
    }
    __syncthreads();

    // --- GEMM: acc[rt][ct][4], rows = wid*32 + rt*16 + frag rows, cols = ct*8
    float acc[2][8][4];
    #pragma unroll
    for (int rt = 0; rt < 2; rt++)
        #pragma unroll
        for (int ct = 0; ct < 8; ct++)
            #pragma unroll
            for (int e = 0; e < 4; e++) acc[rt][ct][e] = 0.0f;

    const int lm = lid >> 3;   // ldmatrix quadrant
    const int lr = lid & 7;

    #pragma unroll
    for (int pass = 0; pass < 3; pass++) {
        const uint32_t Aimg = sbase + ((pass == 2) ? SM_AOL : SM_AOH);
        const uint32_t Bimg = sbase + ((pass == 1) ? SM_BSL : SM_BSH);
        #pragma unroll
        for (int kt = 0; kt < 4; kt++) {
            // A fragments: matrices [r0-7,k0-7],[r8-15,k0-7],[r0-7,k8-15],[r8-15,k8-15]
            uint32_t a[2][4];
            #pragma unroll
            for (int rt = 0; rt < 2; rt++) {
                const int row = wid * 32 + rt * 16 + (lm & 1) * 8 + lr;
                const int kb  = kt * 32 + (lm >> 1) * 16;
                ldm_x4(a[rt], Aimg + row * 128 + (kb ^ ((row & 7) << 4)));
            }
            // B fragments: M symmetric -> col-major B frag = contiguous row pairs
            // matrices [ct_a,k0],[ct_a,k8],[ct_b,k0],[ct_b,k8]
            uint32_t bb[8][2];
            #pragma unroll
            for (int cp = 0; cp < 4; cp++) {
                const int n  = cp * 16 + (lm >> 1) * 8 + lr;
                const int kb = kt * 32 + (lm & 1) * 16;
                ldm_x4(&bb[cp * 2][0], Bimg + n * 128 + (kb ^ ((n & 7) << 4)));
            }
            #pragma unroll
            for (int rt = 0; rt < 2; rt++)
                #pragma unroll
                for (int ct = 0; ct < 8; ct++)
                    mma_bf16(acc[rt][ct], a[rt], bb[ct]);
        }
    }

    // --- Epilogue: val[p] = b + sum_n o[p][n] * (wl[n] + T[p][n])
    const int gid = lid >> 2;
    const int tig = lid & 3;
    const float bval = biases[h];
    const float* wl = reinterpret_cast<const float*>(smem + SM_WL);

    #pragma unroll
    for (int rt = 0; rt < 2; rt++) {
        const int p0 = wid * 32 + rt * 16 + gid;
        const int p1 = p0 + 8;
        float s0 = 0.0f, s1 = 0.0f;
        #pragma unroll
        for (int ct = 0; ct < 8; ct++) {
            const int n0 = ct * 8 + 2 * tig;
            const uint32_t o0off = SWZ((uint32_t)(p0 * 128 + n0 * 2));
            const uint32_t o1off = SWZ((uint32_t)(p1 * 128 + n0 * 2));
            const __nv_bfloat162 h0 = *reinterpret_cast<const __nv_bfloat162*>(smem + SM_AOH + o0off);
            const __nv_bfloat162 l0 = *reinterpret_cast<const __nv_bfloat162*>(smem + SM_AOL + o0off);
            const __nv_bfloat162 h1 = *reinterpret_cast<const __nv_bfloat162*>(smem + SM_AOH + o1off);
            const __nv_bfloat162 l1 = *reinterpret_cast<const __nv_bfloat162*>(smem + SM_AOL + o1off);
            const float2 hf0 = __bfloat1622float2(h0), lf0 = __bfloat1622float2(l0);
            const float2 hf1 = __bfloat1622float2(h1), lf1 = __bfloat1622float2(l1);
            const float2 wlv = *reinterpret_cast<const float2*>(&wl[n0]);
            s0 += (hf0.x + lf0.x) * (wlv.x + acc[rt][ct][0])
                + (hf0.y + lf0.y) * (wlv.y + acc[rt][ct][1]);
            s1 += (hf1.x + lf1.x) * (wlv.x + acc[rt][ct][2])
                + (hf1.y + lf1.y) * (wlv.y + acc[rt][ct][3]);
        }
        s0 += __shfl_xor_sync(0xffffffffu, s0, 1);
        s0 += __shfl_xor_sync(0xffffffffu, s0, 2);
        s1 += __shfl_xor_sync(0xffffffffu, s1, 1);
        s1 += __shfl_xor_sync(0xffffffffu, s1, 2);
        if (tig == 0) {
            out[(size_t)(pbase + p0) * HH + h] = s0 + bval;
            out[(size_t)(pbase + p1) * HH + h] = s1 + bval;
        }
    }
}

// ---------------------------------------------------------------------------
extern "C" void kernel_launch(void* const* d_in, const int* in_sizes, int n_in,
                              void* d_out, int out_size) {
    const float* obs = (const float*)d_in[0];
    const float* w   = (const float*)d_in[1];
    const float* b   = (const float*)d_in[2];
    float* out       = (float*)d_out;

    const int N = in_sizes[0] / (HH * D);   // 1024

    prep_kernel<<<HH, 256>>>(w);

    cudaFuncSetAttribute(vf_kernel, cudaFuncAttributeMaxDynamicSharedMemorySize, SM_TOT);
    dim3 grid(N / 128, HH);                 // (8, 64) = 512 blocks
    vf_kernel<<<grid, TPB, SM_TOT>>>(obs, b, out);
}

// round 7
// speedup vs baseline: 1.5656x; 1.1527x over previous
#include <cuda_runtime.h>
#include <cuda_bf16.h>
#include <cstdint>

#define D        64
#define HH       64
#define D_INPUT  2145
#define TPB      256

typedef unsigned long long ull;

// Pre-swizzled (SW128) bf16 images of M = 1/2(Wu+Wu^T) (diag unhalved),
// split hi/lo. Row = n (output dim), col = k (reduction dim). 64 x 128B per h.
__device__ __align__(16) uint8_t g_Bh[HH][D * 128];
__device__ __align__(16) uint8_t g_Bl[HH][D * 128];
__device__ float g_wl[HH][D];

#define SWZ(off) ((off) ^ (((off) >> 3) & 0x70))

__device__ __forceinline__ uint32_t smem_u32(const void* p) {
    uint32_t a;
    asm("{ .reg .u64 t; cvta.to.shared.u64 t, %1; cvt.u32.u64 %0, t; }" : "=r"(a) : "l"(p));
    return a;
}
__device__ __forceinline__ void ldm_x4(uint32_t* r, uint32_t addr) {
    asm volatile("ldmatrix.sync.aligned.m8n8.x4.shared.b16 {%0,%1,%2,%3}, [%4];"
        : "=r"(r[0]), "=r"(r[1]), "=r"(r[2]), "=r"(r[3]) : "r"(addr));
}
__device__ __forceinline__ void mma_bf16(float* c, const uint32_t* a, const uint32_t* b) {
    asm volatile("mma.sync.aligned.m16n8k16.row.col.f32.bf16.bf16.f32 "
        "{%0,%1,%2,%3}, {%4,%5,%6,%7}, {%8,%9}, {%0,%1,%2,%3};"
        : "+f"(c[0]), "+f"(c[1]), "+f"(c[2]), "+f"(c[3])
        : "r"(a[0]), "r"(a[1]), "r"(a[2]), "r"(a[3]), "r"(b[0]), "r"(b[1]));
}

// ---------------------------------------------------------------------------
// Prep: stage w row into smem coalesced; each of 512 threads emits one
// 8-element (16B) hi chunk + lo chunk of the symmetric M image, float4 stores.
// Packed-triangular: w[h][64 + base(i) + (j-i)], i<=j, base(i)=i*64-i(i-1)/2.
// ---------------------------------------------------------------------------
__global__ void prep_kernel(const float* __restrict__ w) {
    __shared__ float sw[D_INPUT];
    const int h = blockIdx.x;
    for (int i = threadIdx.x; i < D_INPUT; i += 512)
        sw[i] = w[(size_t)h * D_INPUT + i];
    __syncthreads();

    const int t  = threadIdx.x;       // 0..511
    const int n  = t >> 3;            // image row (output dim)
    const int kq = t & 7;             // 8-element chunk within row

    union { __nv_bfloat16 b[8]; float4 f; } hb, lb;
    #pragma unroll
    for (int e = 0; e < 8; e++) {
        const int k = kq * 8 + e;
        const int i = k < n ? k : n;
        const int j = k < n ? n : k;
        const float v = sw[D + i * D - (i * (i - 1)) / 2 + (j - i)];
        const float m = (k == n) ? v : 0.5f * v;
        hb.b[e] = __float2bfloat16_rn(m);
        lb.b[e] = __float2bfloat16_rn(m - __bfloat162float(hb.b[e]));
    }
    const uint32_t sw16 = SWZ((uint32_t)(n * 128 + kq * 16));
    *reinterpret_cast<float4*>(&g_Bh[h][sw16]) = hb.f;
    *reinterpret_cast<float4*>(&g_Bl[h][sw16]) = lb.f;
    if (t < D) g_wl[h][t] = sw[t];
}

// ---------------------------------------------------------------------------
// Main: block = (128-path tile, h), 256 threads / 8 warps.
// Warp (rg = wid&3, ch = wid>>2): computes T strip rows rg*32..+32,
// cols ch*32..+32 via mma.sync, 3 split-bf16 passes (oh*Mh, oh*Ml, ol*Mh).
// Epilogue: per-warp partial of sum_n o*(wl+T) over its col half -> smem,
// then 128 threads combine halves + bias.
// ---------------------------------------------------------------------------
#define SM_AOH  0                       // 128 x 128B bf16 hi (SW128)
#define SM_AOL  16384                   // 128 x 128B bf16 lo
#define SM_BSH  32768                   // 64 x 128B M hi
#define SM_BSL  40960                   // 64 x 128B M lo
#define SM_WL   49152                   // 64 fp32
#define SM_PART 49408                   // 2 x 128 fp32 partials
#define SM_TOT  (SM_PART + 1024)

extern __shared__ char smem[];

__global__ __launch_bounds__(TPB)
void vf_kernel(const float* __restrict__ obs,
               const float* __restrict__ biases,
               float* __restrict__ out) {
    const int h     = blockIdx.y;
    const int pbase = blockIdx.x * 128;
    const int tid   = threadIdx.x;
    const int wid   = tid >> 5;
    const int lid   = tid & 31;
    const int rg    = wid & 3;        // row group: paths rg*32..+32
    const int ch    = wid >> 2;       // col half:  n in ch*32..+32
    const uint32_t sbase = smem_u32(smem);

    // --- Stage M images (pre-swizzled) + linear weights
    {
        const float4* bh4 = reinterpret_cast<const float4*>(&g_Bh[h][0]);
        const float4* bl4 = reinterpret_cast<const float4*>(&g_Bl[h][0]);
        float4* sh4 = reinterpret_cast<float4*>(smem + SM_BSH);
        float4* sl4 = reinterpret_cast<float4*>(smem + SM_BSL);
        #pragma unroll
        for (int k = 0; k < 2; k++) {
            sh4[tid + TPB * k] = bh4[tid + TPB * k];
            sl4[tid + TPB * k] = bl4[tid + TPB * k];
        }
        if (tid < D / 4)
            reinterpret_cast<float4*>(smem + SM_WL)[tid] =
                reinterpret_cast<const float4*>(&g_wl[h][0])[tid];
    }

    // --- Stage obs tile: fp32 coalesced -> bf16 hi/lo, swizzled stores
    {
        #pragma unroll
        for (int k = 0; k < 8; k++) {
            const int f = tid + TPB * k;
            const int p = f >> 4;
            const int q = f & 15;
            const float4 v = reinterpret_cast<const float4*>(obs)
                [(size_t)(pbase + p) * (HH * D / 4) + (size_t)h * (D / 4) + q];
            __nv_bfloat16 hb[4], lb[4];
            const float vf[4] = {v.x, v.y, v.z, v.w};
            #pragma unroll
            for (int e = 0; e < 4; e++) {
                hb[e] = __float2bfloat16_rn(vf[e]);
                lb[e] = __float2bfloat16_rn(vf[e] - __bfloat162float(hb[e]));
            }
            const uint32_t sw = SWZ((uint32_t)(p * 128 + q * 8));
            *reinterpret_cast<ull*>(smem + SM_AOH + sw) = *reinterpret_cast<ull*>(hb);
            *reinterpret_cast<ull*>(smem + SM_AOL + sw) = *reinterpret_cast<ull*>(lb);
        }
    }
    __syncthreads();

    // --- GEMM strip: acc[rt][ct][4] -> rows rg*32+rt*16+frag, cols ch*32+ct*8
    float acc[2][4][4];
    #pragma unroll
    for (int rt = 0; rt < 2; rt++)
        #pragma unroll
        for (int ct = 0; ct < 4; ct++)
            #pragma unroll
            for (int e = 0; e < 4; e++) acc[rt][ct][e] = 0.0f;

    const int lm = lid >> 3;
    const int lr = lid & 7;

    #pragma unroll
    for (int pass = 0; pass < 3; pass++) {
        const uint32_t Aimg = sbase + ((pass == 2) ? SM_AOL : SM_AOH);
        const uint32_t Bimg = sbase + ((pass == 1) ? SM_BSL : SM_BSH);
        #pragma unroll
        for (int kt = 0; kt < 4; kt++) {
            uint32_t a[2][4];
            #pragma unroll
            for (int rt = 0; rt < 2; rt++) {
                const int row = rg * 32 + rt * 16 + (lm & 1) * 8 + lr;
                const int kb  = kt * 32 + (lm >> 1) * 16;
                ldm_x4(a[rt], Aimg + row * 128 + (kb ^ ((row & 7) << 4)));
            }
            uint32_t bb[4][2];
            #pragma unroll
            for (int cp = 0; cp < 2; cp++) {
                const int n  = ch * 32 + cp * 16 + (lm >> 1) * 8 + lr;
                const int kb = kt * 32 + (lm & 1) * 16;
                ldm_x4(&bb[cp * 2][0], Bimg + n * 128 + (kb ^ ((n & 7) << 4)));
            }
            #pragma unroll
            for (int rt = 0; rt < 2; rt++)
                #pragma unroll
                for (int ct = 0; ct < 4; ct++)
                    mma_bf16(acc[rt][ct], a[rt], bb[ct]);
        }
    }

    // --- Per-warp partial: s[p] = sum_{n in col half} o[p][n] * (wl[n] + T[p][n])
    const int gid = lid >> 2;
    const int tig = lid & 3;
    const float* wl = reinterpret_cast<const float*>(smem + SM_WL);
    float* part = reinterpret_cast<float*>(smem + SM_PART);

    #pragma unroll
    for (int rt = 0; rt < 2; rt++) {
        const int p0 = rg * 32 + rt * 16 + gid;
        const int p1 = p0 + 8;
        float s0 = 0.0f, s1 = 0.0f;
        #pragma unroll
        for (int ct = 0; ct < 4; ct++) {
            const int n0 = ch * 32 + ct * 8 + 2 * tig;
            const uint32_t o0off = SWZ((uint32_t)(p0 * 128 + n0 * 2));
            const uint32_t o1off = SWZ((uint32_t)(p1 * 128 + n0 * 2));
            const __nv_bfloat162 h0 = *reinterpret_cast<const __nv_bfloat162*>(smem + SM_AOH + o0off);
            const __nv_bfloat162 l0 = *reinterpret_cast<const __nv_bfloat162*>(smem + SM_AOL + o0off);
            const __nv_bfloat162 h1 = *reinterpret_cast<const __nv_bfloat162*>(smem + SM_AOH + o1off);
            const __nv_bfloat162 l1 = *reinterpret_cast<const __nv_bfloat162*>(smem + SM_AOL + o1off);
            const float2 hf0 = __bfloat1622float2(h0), lf0 = __bfloat1622float2(l0);
            const float2 hf1 = __bfloat1622float2(h1), lf1 = __bfloat1622float2(l1);
            const float2 wlv = *reinterpret_cast<const float2*>(&wl[n0]);
            s0 += (hf0.x + lf0.x) * (wlv.x + acc[rt][ct][0])
                + (hf0.y + lf0.y) * (wlv.y + acc[rt][ct][1]);
            s1 += (hf1.x + lf1.x) * (wlv.x + acc[rt][ct][2])
                + (hf1.y + lf1.y) * (wlv.y + acc[rt][ct][3]);
        }
        s0 += __shfl_xor_sync(0xffffffffu, s0, 1);
        s0 += __shfl_xor_sync(0xffffffffu, s0, 2);
        s1 += __shfl_xor_sync(0xffffffffu, s1, 1);
        s1 += __shfl_xor_sync(0xffffffffu, s1, 2);
        if (tig == 0) {
            part[ch * 128 + p0] = s0;
            part[ch * 128 + p1] = s1;
        }
    }
    __syncthreads();

    // --- Combine halves + bias, coalesced store
    if (tid < 128) {
        const float v = part[tid] + part[128 + tid] + biases[h];
        out[(size_t)(pbase + tid) * HH + h] = v;
    }
}

// ---------------------------------------------------------------------------
extern "C" void kernel_launch(void* const* d_in, const int* in_sizes, int n_in,
                              void* d_out, int out_size) {
    const float* obs = (const float*)d_in[0];
    const float* w   = (const float*)d_in[1];
    const float* b   = (const float*)d_in[2];
    float* out       = (float*)d_out;

    const int N = in_sizes[0] / (HH * D);   // 1024

    prep_kernel<<<HH, 512>>>(w);

    cudaFuncSetAttribute(vf_kernel, cudaFuncAttributeMaxDynamicSharedMemorySize, SM_TOT);
    dim3 grid(N / 128, HH);                 // (8, 64) = 512 blocks x 8 warps
    vf_kernel<<<grid, TPB, SM_TOT>>>(obs, b, out);
}

// round 8
// speedup vs baseline: 1.5690x; 1.0022x over previous
#include <cuda_runtime.h>
#include <cuda_bf16.h>
#include <cstdint>

#define D        64
#define HH       64
#define D_INPUT  2145
#define TPB      128

typedef unsigned long long ull;

// Pre-swizzled (SW128) bf16 images of M = 1/2(Wu+Wu^T) (diag unhalved),
// split hi/lo. Row = n (output dim), col = k (reduction dim). 64 x 128B per h.
__device__ __align__(16) uint8_t g_Bh[HH][D * 128];
__device__ __align__(16) uint8_t g_Bl[HH][D * 128];
__device__ float g_wl[HH][D];

#define SWZ(off) ((off) ^ (((off) >> 3) & 0x70))

__device__ __forceinline__ uint32_t smem_u32(const void* p) {
    uint32_t a;
    asm("{ .reg .u64 t; cvta.to.shared.u64 t, %1; cvt.u32.u64 %0, t; }" : "=r"(a) : "l"(p));
    return a;
}
__device__ __forceinline__ void ldm_x4(uint32_t* r, uint32_t addr) {
    asm volatile("ldmatrix.sync.aligned.m8n8.x4.shared.b16 {%0,%1,%2,%3}, [%4];"
        : "=r"(r[0]), "=r"(r[1]), "=r"(r[2]), "=r"(r[3]) : "r"(addr));
}
__device__ __forceinline__ void mma_bf16(float* c, const uint32_t* a, const uint32_t* b) {
    asm volatile("mma.sync.aligned.m16n8k16.row.col.f32.bf16.bf16.f32 "
        "{%0,%1,%2,%3}, {%4,%5,%6,%7}, {%8,%9}, {%0,%1,%2,%3};"
        : "+f"(c[0]), "+f"(c[1]), "+f"(c[2]), "+f"(c[3])
        : "r"(a[0]), "r"(a[1]), "r"(a[2]), "r"(a[3]), "r"(b[0]), "r"(b[1]));
}
// packed cvt: d.lo = bf16(x), d.hi = bf16(y)
__device__ __forceinline__ uint32_t cvt_bf16x2(float y, float x) {
    uint32_t r;
    asm("cvt.rn.bf16x2.f32 %0, %1, %2;" : "=r"(r) : "f"(y), "f"(x));
    return r;
}
__device__ __forceinline__ float bflo(uint32_t p) { return __uint_as_float(p << 16); }
__device__ __forceinline__ float bfhi(uint32_t p) { return __uint_as_float(p & 0xffff0000u); }

// ---------------------------------------------------------------------------
// Prep: stage w row into smem; 512 threads emit 16B hi + 16B lo chunks of the
// symmetric M image. w[h][64 + base(i) + (j-i)], i<=j, base(i)=i*64-i(i-1)/2.
// ---------------------------------------------------------------------------
__global__ void prep_kernel(const float* __restrict__ w) {
    __shared__ float sw[D_INPUT];
    const int h = blockIdx.x;
    for (int i = threadIdx.x; i < D_INPUT; i += 512)
        sw[i] = w[(size_t)h * D_INPUT + i];
    __syncthreads();

    const int t  = threadIdx.x;
    const int n  = t >> 3;
    const int kq = t & 7;

    union { __nv_bfloat16 b[8]; float4 f; } hb, lb;
    #pragma unroll
    for (int e = 0; e < 8; e++) {
        const int k = kq * 8 + e;
        const int i = k < n ? k : n;
        const int j = k < n ? n : k;
        const float v = sw[D + i * D - (i * (i - 1)) / 2 + (j - i)];
        const float m = (k == n) ? v : 0.5f * v;
        hb.b[e] = __float2bfloat16_rn(m);
        lb.b[e] = __float2bfloat16_rn(m - __bfloat162float(hb.b[e]));
    }
    const uint32_t sw16 = SWZ((uint32_t)(n * 128 + kq * 16));
    *reinterpret_cast<float4*>(&g_Bh[h][sw16]) = hb.f;
    *reinterpret_cast<float4*>(&g_Bl[h][sw16]) = lb.f;
    if (t < D) g_wl[h][t] = sw[t];
}

// ---------------------------------------------------------------------------
// Main: block = (64-path tile, h), 128 threads / 4 warps. Warp rg owns rows
// rg*16..+16, ALL 64 cols: acc[8][4]. 3 split-bf16 passes. Epilogue folds
// val = b + sum_n o*(wl+T) with a 4-lane shfl reduce; direct store.
// ---------------------------------------------------------------------------
#define SM_AOH  0                       // 64 x 128B bf16 hi (SW128)
#define SM_AOL  8192                    // 64 x 128B bf16 lo
#define SM_BSH  16384                   // 64 x 128B M hi
#define SM_BSL  24576                   // 64 x 128B M lo
#define SM_WL   32768                   // 64 fp32
#define SM_TOT  (SM_WL + 256)           // 33024 B

extern __shared__ char smem[];

__global__ __launch_bounds__(TPB, 5)
void vf_kernel(const float* __restrict__ obs,
               const float* __restrict__ biases,
               float* __restrict__ out) {
    const int h     = blockIdx.y;
    const int pbase = blockIdx.x * 64;
    const int tid   = threadIdx.x;
    const int wid   = tid >> 5;       // = row group rg
    const int lid   = tid & 31;
    const uint32_t sbase = smem_u32(smem);

    // --- Stage M images (pre-swizzled) + linear weights
    {
        const float4* bh4 = reinterpret_cast<const float4*>(&g_Bh[h][0]);
        const float4* bl4 = reinterpret_cast<const float4*>(&g_Bl[h][0]);
        float4* sh4 = reinterpret_cast<float4*>(smem + SM_BSH);
        float4* sl4 = reinterpret_cast<float4*>(smem + SM_BSL);
        #pragma unroll
        for (int k = 0; k < 4; k++) {
            sh4[tid + TPB * k] = bh4[tid + TPB * k];
            sl4[tid + TPB * k] = bl4[tid + TPB * k];
        }
        if (tid < D / 4)
            reinterpret_cast<float4*>(smem + SM_WL)[tid] =
                reinterpret_cast<const float4*>(&g_wl[h][0])[tid];
    }

    // --- Stage obs tile: 64 rows x 16 float4, 8/thread; packed bf16 cvt
    {
        #pragma unroll
        for (int k = 0; k < 8; k++) {
            const int f = tid + TPB * k;
            const int p = f >> 4;
            const int q = f & 15;
            const float4 v = reinterpret_cast<const float4*>(obs)
                [(size_t)(pbase + p) * (HH * D / 4) + (size_t)h * (D / 4) + q];
            const uint32_t h01 = cvt_bf16x2(v.y, v.x);
            const uint32_t h23 = cvt_bf16x2(v.w, v.z);
            const uint32_t l01 = cvt_bf16x2(v.y - bfhi(h01), v.x - bflo(h01));
            const uint32_t l23 = cvt_bf16x2(v.w - bfhi(h23), v.z - bflo(h23));
            const uint32_t sw = SWZ((uint32_t)(p * 128 + q * 8));
            *reinterpret_cast<uint2*>(smem + SM_AOH + sw) = make_uint2(h01, h23);
            *reinterpret_cast<uint2*>(smem + SM_AOL + sw) = make_uint2(l01, l23);
        }
    }
    __syncthreads();

    // --- GEMM strip: warp rows wid*16..+16, cols 0..64; acc[ct][4]
    float acc[8][4];
    #pragma unroll
    for (int ct = 0; ct < 8; ct++)
        #pragma unroll
        for (int e = 0; e < 4; e++) acc[ct][e] = 0.0f;

    const int lm = lid >> 3;
    const int lr = lid & 7;

    #pragma unroll
    for (int pass = 0; pass < 3; pass++) {
        const uint32_t Aimg = sbase + ((pass == 2) ? SM_AOL : SM_AOH);
        const uint32_t Bimg = sbase + ((pass == 1) ? SM_BSL : SM_BSH);
        #pragma unroll
        for (int kt = 0; kt < 4; kt++) {
            // A fragment: 16 rows x 16 k
            uint32_t a[4];
            {
                const int row = wid * 16 + (lm & 1) * 8 + lr;
                const int kb  = kt * 32 + (lm >> 1) * 16;
                ldm_x4(a, Aimg + row * 128 + (kb ^ ((row & 7) << 4)));
            }
            // B fragments: 4 x (16 n x 16 k) -> 8 col tiles
            uint32_t bb[8][2];
            #pragma unroll
            for (int cp = 0; cp < 4; cp++) {
                const int n  = cp * 16 + (lm >> 1) * 8 + lr;
                const int kb = kt * 32 + (lm & 1) * 16;
                ldm_x4(&bb[cp * 2][0], Bimg + n * 128 + (kb ^ ((n & 7) << 4)));
            }
            #pragma unroll
            for (int ct = 0; ct < 8; ct++)
                mma_bf16(acc[ct], a, bb[ct]);
        }
    }

    // --- Epilogue: val[p] = b + sum_n o[p][n] * (wl[n] + T[p][n])
    const int gid = lid >> 2;
    const int tig = lid & 3;
    const float* wl = reinterpret_cast<const float*>(smem + SM_WL);

    const int p0 = wid * 16 + gid;
    const int p1 = p0 + 8;
    float s0 = 0.0f, s1 = 0.0f;
    #pragma unroll
    for (int ct = 0; ct < 8; ct++) {
        const int n0 = ct * 8 + 2 * tig;
        const uint32_t o0off = SWZ((uint32_t)(p0 * 128 + n0 * 2));
        const uint32_t o1off = SWZ((uint32_t)(p1 * 128 + n0 * 2));
        const uint32_t h0 = *reinterpret_cast<const uint32_t*>(smem + SM_AOH + o0off);
        const uint32_t l0 = *reinterpret_cast<const uint32_t*>(smem + SM_AOL + o0off);
        const uint32_t h1 = *reinterpret_cast<const uint32_t*>(smem + SM_AOH + o1off);
        const uint32_t l1 = *reinterpret_cast<const uint32_t*>(smem + SM_AOL + o1off);
        const float2 wlv = *reinterpret_cast<const float2*>(&wl[n0]);
        const float u0 = wlv.x + acc[ct][0], u1 = wlv.y + acc[ct][1];
        const float w0 = wlv.x + acc[ct][2], w1 = wlv.y + acc[ct][3];
        s0 = fmaf(bflo(h0) + bflo(l0), u0, s0);
        s0 = fmaf(bfhi(h0) + bfhi(l0), u1, s0);
        s1 = fmaf(bflo(h1) + bflo(l1), w0, s1);
        s1 = fmaf(bfhi(h1) + bfhi(l1), w1, s1);
    }
    s0 += __shfl_xor_sync(0xffffffffu, s0, 1);
    s0 += __shfl_xor_sync(0xffffffffu, s0, 2);
    s1 += __shfl_xor_sync(0xffffffffu, s1, 1);
    s1 += __shfl_xor_sync(0xffffffffu, s1, 2);
    if (tig == 0) {
        const float bval = biases[h];
        out[(size_t)(pbase + p0) * HH + h] = s0 + bval;
        out[(size_t)(pbase + p1) * HH + h] = s1 + bval;
    }
}

// ---------------------------------------------------------------------------
extern "C" void kernel_launch(void* const* d_in, const int* in_sizes, int n_in,
                              void* d_out, int out_size) {
    const float* obs = (const float*)d_in[0];
    const float* w   = (const float*)d_in[1];
    const float* b   = (const float*)d_in[2];
    float* out       = (float*)d_out;

    const int N = in_sizes[0] / (HH * D);   // 1024

    prep_kernel<<<HH, 512>>>(w);

    cudaFuncSetAttribute(vf_kernel, cudaFuncAttributeMaxDynamicSharedMemorySize, SM_TOT);
    dim3 grid(N / 64, HH);                  // (16, 64) = 1024 blocks x 4 warps
    vf_kernel<<<grid, TPB, SM_TOT>>>(obs, b, out);
}

// round 9
// speedup vs baseline: 1.8200x; 1.1600x over previous
#include <cuda_runtime.h>
#include <cuda_fp16.h>
#include <cstdint>

#define D        64
#define HH       64
#define D_INPUT  2145
#define TPB      128

// Pre-swizzled (SW128) fp16 images of M = 1/2(Wu+Wu^T) (diag unhalved),
// split hi/lo so M is effectively exact. Row = n (output), col = k. 64 x 128B.
__device__ __align__(16) uint8_t g_Mh[HH][D * 128];
__device__ __align__(16) uint8_t g_Ml[HH][D * 128];
__device__ float g_wl[HH][D];

#define SWZ(off) ((off) ^ (((off) >> 3) & 0x70))

__device__ __forceinline__ uint32_t smem_u32(const void* p) {
    uint32_t a;
    asm("{ .reg .u64 t; cvta.to.shared.u64 t, %1; cvt.u32.u64 %0, t; }" : "=r"(a) : "l"(p));
    return a;
}
__device__ __forceinline__ void ldm_x4(uint32_t* r, uint32_t addr) {
    asm volatile("ldmatrix.sync.aligned.m8n8.x4.shared.b16 {%0,%1,%2,%3}, [%4];"
        : "=r"(r[0]), "=r"(r[1]), "=r"(r[2]), "=r"(r[3]) : "r"(addr));
}
__device__ __forceinline__ void mma_f16(float* c, const uint32_t* a, const uint32_t* b) {
    asm volatile("mma.sync.aligned.m16n8k16.row.col.f32.f16.f16.f32 "
        "{%0,%1,%2,%3}, {%4,%5,%6,%7}, {%8,%9}, {%0,%1,%2,%3};"
        : "+f"(c[0]), "+f"(c[1]), "+f"(c[2]), "+f"(c[3])
        : "r"(a[0]), "r"(a[1]), "r"(a[2]), "r"(a[3]), "r"(b[0]), "r"(b[1]));
}

// ---------------------------------------------------------------------------
// Prep: stage w row into smem; 512 threads emit one 16B hi + 16B lo chunk of
// the symmetric M image (fp16). w[h][64+base(i)+(j-i)], base(i)=i*64-i(i-1)/2.
// ---------------------------------------------------------------------------
__global__ void prep_kernel(const float* __restrict__ w) {
    __shared__ float sw[D_INPUT];
    const int h = blockIdx.x;
    for (int i = threadIdx.x; i < D_INPUT; i += 512)
        sw[i] = w[(size_t)h * D_INPUT + i];
    __syncthreads();

    const int t  = threadIdx.x;
    const int n  = t >> 3;
    const int kq = t & 7;

    union { __half b[8]; float4 f; } hb, lb;
    #pragma unroll
    for (int e = 0; e < 8; e++) {
        const int k = kq * 8 + e;
        const int i = k < n ? k : n;
        const int j = k < n ? n : k;
        const float v = sw[D + i * D - (i * (i - 1)) / 2 + (j - i)];
        const float m = (k == n) ? v : 0.5f * v;
        hb.b[e] = __float2half_rn(m);
        lb.b[e] = __float2half_rn(m - __half2float(hb.b[e]));
    }
    const uint32_t sw16 = SWZ((uint32_t)(n * 128 + kq * 16));
    *reinterpret_cast<float4*>(&g_Mh[h][sw16]) = hb.f;
    *reinterpret_cast<float4*>(&g_Ml[h][sw16]) = lb.f;
    if (t < D) g_wl[h][t] = sw[t];
}

// ---------------------------------------------------------------------------
// Main: block = (64-path tile, h), 128 threads / 4 warps. Warp wid owns rows
// wid*16..+16, all 64 cols. 2 fp16 passes sharing the A fragment:
//   T = O*(Mh + Ml),  val = b + sum_n o_n*(wl_n + T_n)
// ---------------------------------------------------------------------------
#define SM_O    0                       // 64 x 128B fp16 obs image (SW128)
#define SM_MH   8192                    // 64 x 128B M hi
#define SM_ML   16384                   // 64 x 128B M lo
#define SM_WL   24576                   // 64 fp32
#define SM_TOT  (SM_WL + 256)           // 24832 B

extern __shared__ char smem[];

__global__ __launch_bounds__(TPB, 5)
void vf_kernel(const float* __restrict__ obs,
               const float* __restrict__ biases,
               float* __restrict__ out) {
    const int h     = blockIdx.y;
    const int pbase = blockIdx.x * 64;
    const int tid   = threadIdx.x;
    const int wid   = tid >> 5;
    const int lid   = tid & 31;
    const uint32_t sbase = smem_u32(smem);

    // --- Stage M images (pre-swizzled, fp16): 512 float4 each, 4/thread
    {
        const float4* mh4 = reinterpret_cast<const float4*>(&g_Mh[h][0]);
        const float4* ml4 = reinterpret_cast<const float4*>(&g_Ml[h][0]);
        float4* sh4 = reinterpret_cast<float4*>(smem + SM_MH);
        float4* sl4 = reinterpret_cast<float4*>(smem + SM_ML);
        #pragma unroll
        for (int k = 0; k < 4; k++) {
            sh4[tid + TPB * k] = mh4[tid + TPB * k];
            sl4[tid + TPB * k] = ml4[tid + TPB * k];
        }
        if (tid < D / 4)
            reinterpret_cast<float4*>(smem + SM_WL)[tid] =
                reinterpret_cast<const float4*>(&g_wl[h][0])[tid];
    }

    // --- Stage obs tile: 64 rows x 16 float4 fp32 -> single fp16 image
    {
        #pragma unroll
        for (int k = 0; k < 8; k++) {
            const int f = tid + TPB * k;
            const int p = f >> 4;
            const int q = f & 15;
            const float4 v = reinterpret_cast<const float4*>(obs)
                [(size_t)(pbase + p) * (HH * D / 4) + (size_t)h * (D / 4) + q];
            const __half2 h01 = __floats2half2_rn(v.x, v.y);
            const __half2 h23 = __floats2half2_rn(v.z, v.w);
            const uint32_t sw = SWZ((uint32_t)(p * 128 + q * 8));
            *reinterpret_cast<uint2*>(smem + SM_O + sw) =
                make_uint2(*reinterpret_cast<const uint32_t*>(&h01),
                           *reinterpret_cast<const uint32_t*>(&h23));
        }
    }
    __syncthreads();

    // --- GEMM strip: warp rows wid*16..+16, cols 0..64; acc[ct][4]
    float acc[8][4];
    #pragma unroll
    for (int ct = 0; ct < 8; ct++)
        #pragma unroll
        for (int e = 0; e < 4; e++) acc[ct][e] = 0.0f;

    const int lm = lid >> 3;
    const int lr = lid & 7;

    #pragma unroll
    for (int kt = 0; kt < 4; kt++) {
        // A fragment (shared by both passes): 16 rows x 16 k
        uint32_t a[4];
        {
            const int row = wid * 16 + (lm & 1) * 8 + lr;
            const int kb  = kt * 32 + (lm >> 1) * 16;
            ldm_x4(a, sbase + SM_O + row * 128 + (kb ^ ((row & 7) << 4)));
        }
        // B fragments for Mh and Ml: 4 x (16 n x 16 k) each -> 8 col tiles
        uint32_t bh[8][2], bl[8][2];
        #pragma unroll
        for (int cp = 0; cp < 4; cp++) {
            const int n  = cp * 16 + (lm >> 1) * 8 + lr;
            const int kb = kt * 32 + (lm & 1) * 16;
            const uint32_t off = n * 128 + (kb ^ ((n & 7) << 4));
            ldm_x4(&bh[cp * 2][0], sbase + SM_MH + off);
            ldm_x4(&bl[cp * 2][0], sbase + SM_ML + off);
        }
        #pragma unroll
        for (int ct = 0; ct < 8; ct++) {
            mma_f16(acc[ct], a, bh[ct]);
            mma_f16(acc[ct], a, bl[ct]);
        }
    }

    // --- Epilogue: val[p] = b + sum_n o[p][n] * (wl[n] + T[p][n])
    const int gid = lid >> 2;
    const int tig = lid & 3;
    const float* wl = reinterpret_cast<const float*>(smem + SM_WL);

    const int p0 = wid * 16 + gid;
    const int p1 = p0 + 8;
    float s0 = 0.0f, s1 = 0.0f;
    #pragma unroll
    for (int ct = 0; ct < 8; ct++) {
        const int n0 = ct * 8 + 2 * tig;
        const __half2 o0 = *reinterpret_cast<const __half2*>(
            smem + SM_O + SWZ((uint32_t)(p0 * 128 + n0 * 2)));
        const __half2 o1 = *reinterpret_cast<const __half2*>(
            smem + SM_O + SWZ((uint32_t)(p1 * 128 + n0 * 2)));
        const float2 of0 = __half22float2(o0);
        const float2 of1 = __half22float2(o1);
        const float2 wlv = *reinterpret_cast<const float2*>(&wl[n0]);
        s0 = fmaf(of0.x, wlv.x + acc[ct][0], s0);
        s0 = fmaf(of0.y, wlv.y + acc[ct][1], s0);
        s1 = fmaf(of1.x, wlv.x + acc[ct][2], s1);
        s1 = fmaf(of1.y, wlv.y + acc[ct][3], s1);
    }
    s0 += __shfl_xor_sync(0xffffffffu, s0, 1);
    s0 += __shfl_xor_sync(0xffffffffu, s0, 2);
    s1 += __shfl_xor_sync(0xffffffffu, s1, 1);
    s1 += __shfl_xor_sync(0xffffffffu, s1, 2);
    if (tig == 0) {
        const float bval = biases[h];
        out[(size_t)(pbase + p0) * HH + h] = s0 + bval;
        out[(size_t)(pbase + p1) * HH + h] = s1 + bval;
    }
}

// ---------------------------------------------------------------------------
extern "C" void kernel_launch(void* const* d_in, const int* in_sizes, int n_in,
                              void* d_out, int out_size) {
    const float* obs = (const float*)d_in[0];
    const float* w   = (const float*)d_in[1];
    const float* b   = (const float*)d_in[2];
    float* out       = (float*)d_out;

    const int N = in_sizes[0] / (HH * D);   // 1024

    prep_kernel<<<HH, 512>>>(w);

    cudaFuncSetAttribute(vf_kernel, cudaFuncAttributeMaxDynamicSharedMemorySize, SM_TOT);
    dim3 grid(N / 64, HH);                  // (16, 64) = 1024 blocks x 4 warps
    vf_kernel<<<grid, TPB, SM_TOT>>>(obs, b, out);
}

// round 10
// speedup vs baseline: 2.1731x; 1.1940x over previous
#include <cuda_runtime.h>
#include <cuda_fp16.h>
#include <cstdint>

#define D        64
#define HH       64
#define D_INPUT  2145
#define TPB      128

// Pre-swizzled (SW128) fp16 image of M = 1/2(Wu+Wu^T) (diag unhalved).
// Row = n (output dim), col = k (reduction dim). 64 x 128B per h.
__device__ __align__(16) uint8_t g_M[HH][D * 128];
__device__ float g_wl[HH][D];

#define SWZ(off) ((off) ^ (((off) >> 3) & 0x70))

__device__ __forceinline__ uint32_t smem_u32(const void* p) {
    uint32_t a;
    asm("{ .reg .u64 t; cvta.to.shared.u64 t, %1; cvt.u32.u64 %0, t; }" : "=r"(a) : "l"(p));
    return a;
}
__device__ __forceinline__ void ldm_x4(uint32_t* r, uint32_t addr) {
    asm volatile("ldmatrix.sync.aligned.m8n8.x4.shared.b16 {%0,%1,%2,%3}, [%4];"
        : "=r"(r[0]), "=r"(r[1]), "=r"(r[2]), "=r"(r[3]) : "r"(addr));
}
__device__ __forceinline__ void mma_f16(float* c, const uint32_t* a, const uint32_t* b) {
    asm volatile("mma.sync.aligned.m16n8k16.row.col.f32.f16.f16.f32 "
        "{%0,%1,%2,%3}, {%4,%5,%6,%7}, {%8,%9}, {%0,%1,%2,%3};"
        : "+f"(c[0]), "+f"(c[1]), "+f"(c[2]), "+f"(c[3])
        : "r"(a[0]), "r"(a[1]), "r"(a[2]), "r"(a[3]), "r"(b[0]), "r"(b[1]));
}

// ---------------------------------------------------------------------------
// Prep: stage w row into smem; 512 threads emit one 16B fp16 chunk of the
// symmetric M image. w[h][64+base(i)+(j-i)], base(i)=i*64-i(i-1)/2.
// ---------------------------------------------------------------------------
__global__ void prep_kernel(const float* __restrict__ w) {
    __shared__ float sw[D_INPUT];
    const int h = blockIdx.x;
    for (int i = threadIdx.x; i < D_INPUT; i += 512)
        sw[i] = w[(size_t)h * D_INPUT + i];
    __syncthreads();

    const int t  = threadIdx.x;
    const int n  = t >> 3;
    const int kq = t & 7;

    union { __half b[8]; float4 f; } hb;
    #pragma unroll
    for (int e = 0; e < 8; e++) {
        const int k = kq * 8 + e;
        const int i = k < n ? k : n;
        const int j = k < n ? n : k;
        const float v = sw[D + i * D - (i * (i - 1)) / 2 + (j - i)];
        hb.b[e] = __float2half_rn((k == n) ? v : 0.5f * v);
    }
    const uint32_t sw16 = SWZ((uint32_t)(n * 128 + kq * 16));
    *reinterpret_cast<float4*>(&g_M[h][sw16]) = hb.f;
    if (t < D) g_wl[h][t] = sw[t];
}

// ---------------------------------------------------------------------------
// Main: block = (64-path tile, h), 128 threads / 4 warps. Warp wid owns rows
// wid*16..+16, all 64 cols. Single fp16 pass:
//   T = O*M,  val = b + sum_n o_n*(wl_n + T_n)
// ---------------------------------------------------------------------------
#define SM_O    0                       // 64 x 128B fp16 obs image (SW128)
#define SM_M    8192                    // 64 x 128B fp16 M image
#define SM_WL   16384                   // 64 fp32
#define SM_TOT  (SM_WL + 256)           // 16640 B

extern __shared__ char smem[];

__global__ __launch_bounds__(TPB, 6)
void vf_kernel(const float* __restrict__ obs,
               const float* __restrict__ biases,
               float* __restrict__ out) {
    const int h     = blockIdx.y;
    const int pbase = blockIdx.x * 64;
    const int tid   = threadIdx.x;
    const int wid   = tid >> 5;
    const int lid   = tid & 31;
    const uint32_t sbase = smem_u32(smem);

    // --- Stage obs tile first (front-batched LDGs): 64 rows x 16 float4
    float4 ov[8];
    #pragma unroll
    for (int k = 0; k < 8; k++) {
        const int f = tid + TPB * k;
        const int p = f >> 4;
        const int q = f & 15;
        ov[k] = reinterpret_cast<const float4*>(obs)
            [(size_t)(pbase + p) * (HH * D / 4) + (size_t)h * (D / 4) + q];
    }

    // --- Stage M image (pre-swizzled fp16): 512 float4, 4/thread; + wl
    {
        const float4* m4 = reinterpret_cast<const float4*>(&g_M[h][0]);
        float4* sm4 = reinterpret_cast<float4*>(smem + SM_M);
        #pragma unroll
        for (int k = 0; k < 4; k++) sm4[tid + TPB * k] = m4[tid + TPB * k];
        if (tid < D / 4)
            reinterpret_cast<float4*>(smem + SM_WL)[tid] =
                reinterpret_cast<const float4*>(&g_wl[h][0])[tid];
    }

    // --- Convert + store obs image
    #pragma unroll
    for (int k = 0; k < 8; k++) {
        const int f = tid + TPB * k;
        const int p = f >> 4;
        const int q = f & 15;
        const __half2 h01 = __floats2half2_rn(ov[k].x, ov[k].y);
        const __half2 h23 = __floats2half2_rn(ov[k].z, ov[k].w);
        const uint32_t sw = SWZ((uint32_t)(p * 128 + q * 8));
        *reinterpret_cast<uint2*>(smem + SM_O + sw) =
            make_uint2(*reinterpret_cast<const uint32_t*>(&h01),
                       *reinterpret_cast<const uint32_t*>(&h23));
    }
    __syncthreads();

    // --- GEMM strip: warp rows wid*16..+16, cols 0..64; acc[ct][4]
    float acc[8][4];
    #pragma unroll
    for (int ct = 0; ct < 8; ct++)
        #pragma unroll
        for (int e = 0; e < 4; e++) acc[ct][e] = 0.0f;

    const int lm = lid >> 3;
    const int lr = lid & 7;

    #pragma unroll
    for (int kt = 0; kt < 4; kt++) {
        uint32_t a[4];
        {
            const int row = wid * 16 + (lm & 1) * 8 + lr;
            const int kb  = kt * 32 + (lm >> 1) * 16;
            ldm_x4(a, sbase + SM_O + row * 128 + (kb ^ ((row & 7) << 4)));
        }
        uint32_t bb[8][2];
        #pragma unroll
        for (int cp = 0; cp < 4; cp++) {
            const int n  = cp * 16 + (lm >> 1) * 8 + lr;
            const int kb = kt * 32 + (lm & 1) * 16;
            ldm_x4(&bb[cp * 2][0], sbase + SM_M + n * 128 + (kb ^ ((n & 7) << 4)));
        }
        #pragma unroll
        for (int ct = 0; ct < 8; ct++)
            mma_f16(acc[ct], a, bb[ct]);
    }

    // --- Epilogue: val[p] = b + sum_n o[p][n] * (wl[n] + T[p][n])
    const int gid = lid >> 2;
    const int tig = lid & 3;
    const float* wl = reinterpret_cast<const float*>(smem + SM_WL);

    const int p0 = wid * 16 + gid;
    const int p1 = p0 + 8;
    float s0 = 0.0f, s1 = 0.0f;
    #pragma unroll
    for (int ct = 0; ct < 8; ct++) {
        const int n0 = ct * 8 + 2 * tig;
        const __half2 o0 = *reinterpret_cast<const __half2*>(
            smem + SM_O + SWZ((uint32_t)(p0 * 128 + n0 * 2)));
        const __half2 o1 = *reinterpret_cast<const __half2*>(
            smem + SM_O + SWZ((uint32_t)(p1 * 128 + n0 * 2)));
        const float2 of0 = __half22float2(o0);
        const float2 of1 = __half22float2(o1);
        const float2 wlv = *reinterpret_cast<const float2*>(&wl[n0]);
        s0 = fmaf(of0.x, wlv.x + acc[ct][0], s0);
        s0 = fmaf(of0.y, wlv.y + acc[ct][1], s0);
        s1 = fmaf(of1.x, wlv.x + acc[ct][2], s1);
        s1 = fmaf(of1.y, wlv.y + acc[ct][3], s1);
    }
    s0 += __shfl_xor_sync(0xffffffffu, s0, 1);
    s0 += __shfl_xor_sync(0xffffffffu, s0, 2);
    s1 += __shfl_xor_sync(0xffffffffu, s1, 1);
    s1 += __shfl_xor_sync(0xffffffffu, s1, 2);
    if (tig == 0) {
        const float bval = biases[h];
        out[(size_t)(pbase + p0) * HH + h] = s0 + bval;
        out[(size_t)(pbase + p1) * HH + h] = s1 + bval;
    }
}

// ---------------------------------------------------------------------------
extern "C" void kernel_launch(void* const* d_in, const int* in_sizes, int n_in,
                              void* d_out, int out_size) {
    const float* obs = (const float*)d_in[0];
    const float* w   = (const float*)d_in[1];
    const float* b   = (const float*)d_in[2];
    float* out       = (float*)d_out;

    const int N = in_sizes[0] / (HH * D);   // 1024

    prep_kernel<<<HH, 512>>>(w);

    cudaFuncSetAttribute(vf_kernel, cudaFuncAttributeMaxDynamicSharedMemorySize, SM_TOT);
    dim3 grid(N / 64, HH);                  // (16, 64) = 1024 blocks x 4 warps
    vf_kernel<<<grid, TPB, SM_TOT>>>(obs, b, out);
}